// round 16
// baseline (speedup 1.0000x reference)
#include <cuda_runtime.h>
#include <cuda_fp16.h>
#include <mma.h>
#include <cstdint>
#include <type_traits>

using namespace nvcuda;

// Problem dims (fixed by the dataset)
#define D_    1024
#define SQ    1024
#define SK    1024
#define BATCH 8
#define NH    8
#define DH    128

// ---------------- scratch (device globals: no allocation allowed) ----------------
__device__ __half g_memH[(size_t)BATCH * SK * D_];        // fp16(memory)            [8192,1024]
__device__ __half g_cat[(size_t)BATCH * SQ * 2 * D_];     // [fp16(dec) | attn@V]    [8192,2048]
__device__ __half g_KVh[(size_t)BATCH * SK * 2 * D_];     // [K | V] packed          [8192,2048]
__device__ __half g_Qh[(size_t)BATCH * SQ * D_];          // fp16(dec @ Wq)
__device__ __half g_Ph[(size_t)NH * BATCH * SQ * SK];     // fp16(normalized attn)   128MB
__device__ __half g_Wh[(size_t)5 * 1024 * 1024];          // [Wk|Wv] packed 2M | Wq 1M | Wf 2M
__device__ float  g_Y[(size_t)BATCH * SQ * D_];           // concat @ Wf (fp32)
__device__ float  g_partial[(size_t)NH * BATCH * SQ * 16];// row-sum partials [65536][16]
__device__ int    g_mask_kind;                            // 0=int32, 1=byte, 2=float32

// ---------------- helpers ----------------
__device__ __forceinline__ void cp16(void* smem_dst, const void* gsrc) {
    uint32_t s = (uint32_t)__cvta_generic_to_shared(smem_dst);
    asm volatile("cp.async.cg.shared.global [%0], [%1], 16;\n" :: "r"(s), "l"(gsrc));
}
__device__ __forceinline__ void cp_commit() { asm volatile("cp.async.commit_group;\n"); }
__device__ __forceinline__ void cp_wait2()  { asm volatile("cp.async.wait_group 2;\n"); }

// ---------------- reductions ----------------
__device__ __forceinline__ float blockReduceSum(float v) {
    __shared__ float sh[8];
    __syncthreads();
    #pragma unroll
    for (int o = 16; o > 0; o >>= 1) v += __shfl_xor_sync(0xffffffffu, v, o);
    int lane = threadIdx.x & 31, w = threadIdx.x >> 5;
    if (lane == 0) sh[w] = v;
    __syncthreads();
    if (w == 0) {
        float x = (lane < 8) ? sh[lane] : 0.0f;
        #pragma unroll
        for (int o = 4; o > 0; o >>= 1) x += __shfl_xor_sync(0xffffffffu, x, o);
        if (lane == 0) sh[0] = x;
    }
    __syncthreads();
    return sh[0];
}

// ---------------- fp32 -> fp16 pack helper ----------------
__device__ __forceinline__ uint4 pack_h8(float4 a, float4 b) {
    __half2 h0 = __floats2half2_rn(a.x, a.y);
    __half2 h1 = __floats2half2_rn(a.z, a.w);
    __half2 h2 = __floats2half2_rn(b.x, b.y);
    __half2 h3 = __floats2half2_rn(b.z, b.w);
    uint4 u;
    u.x = *reinterpret_cast<unsigned*>(&h0);
    u.y = *reinterpret_cast<unsigned*>(&h1);
    u.z = *reinterpret_cast<unsigned*>(&h2);
    u.w = *reinterpret_cast<unsigned*>(&h3);
    return u;
}

// memory fp32 -> fp16 (8 elems/thread)
__global__ __launch_bounds__(256)
void f2h_kernel(const float4* __restrict__ in, uint4* __restrict__ out, int n8)
{
    int i = blockIdx.x * 256 + threadIdx.x;
    if (i < n8) out[i] = pack_h8(in[2 * i], in[2 * i + 1]);
}

// dec fp32 [8192,1024] -> fp16 into left half of cat [8192,2048]
__global__ __launch_bounds__(256)
void dec2cat_kernel(const float4* __restrict__ dec, __half* __restrict__ cat)
{
    int i = blockIdx.x * 256 + threadIdx.x;     // 1M threads, 8 elems each
    int row = i >> 7, c8 = i & 127;
    uint4 u = pack_h8(dec[2 * i], dec[2 * i + 1]);
    *reinterpret_cast<uint4*>(cat + (size_t)row * 2048 + c8 * 8) = u;
}

// Weight conversion into packed fp16 layouts (Wkv [1024,2048] | Wq | Wf)
__global__ __launch_bounds__(256)
void wconv_kernel(const float4* __restrict__ Wk, const float4* __restrict__ Wv,
                  const float4* __restrict__ Wq, const float4* __restrict__ Wf,
                  uint4* __restrict__ Wh)
{
    int i = blockIdx.x * 256 + threadIdx.x;     // 0 .. 655359  (5M halfs / 8)
    const float4* src;
    int j;
    if (i < 262144) {                  // Wkv packed region: [1024, 2048] halfs
        int row = i >> 8;
        int c8  = i & 255;
        if (c8 < 128) { src = Wk; j = row * 128 + c8; }
        else          { src = Wv; j = row * 128 + (c8 - 128); }
    } else if (i < 393216) { src = Wq; j = i - 262144; }
    else                   { src = Wf; j = i - 393216; }
    Wh[i] = pack_h8(src[2 * j], src[2 * j + 1]);
}

// ---------------- generic batched fp16 wmma GEMM ----------------
// 128 threads / 4 warps, BM=BN=128, warp tile 64x64 (4x4 fragments), BK=32.
#define BM 128
#define BN 128
#define BK 32
#define APADh  40    // halfs: 80B row stride (16B multiple)
#define BNPADh 136   // halfs: 272B row stride (16B multiple)
#define NST 3

template<bool BCOL, typename OutT>
__global__ __launch_bounds__(128, 2)
void gemm_h(const __half* __restrict__ Abase, long long sA1, long long sA2, int lda,
            const __half* __restrict__ Bbase, long long sB1, long long sB2, int ldb,
            OutT*         __restrict__ Cbase, long long sC1, long long sC2, int ldc,
            int K, int Z2, float alpha)
{
    extern __shared__ __align__(16) __half smh[];
    constexpr int ASTG = BM * APADh;                        // 5120 halfs
    constexpr int BSTG = BCOL ? (BM * APADh) : (BK * BNPADh);
    __half* As = smh;
    __half* Bs = smh + NST * ASTG;

    const int z  = blockIdx.z;
    const int z1 = z / Z2, z2 = z % Z2;
    const __half* A = Abase + (size_t)z1 * sA1 + (size_t)z2 * sA2;
    const __half* B = Bbase + (size_t)z1 * sB1 + (size_t)z2 * sB2;
    OutT*         C = Cbase + (size_t)z1 * sC1 + (size_t)z2 * sC2;

    const int m0 = blockIdx.y * BM;
    const int n0 = blockIdx.x * BN;

    const int tid    = threadIdx.x;
    const int wid    = tid >> 5;
    const int warp_m = wid & 1;   // 2 warps along M (64 rows each)
    const int warp_n = wid >> 1;  // 2 warps along N (64 cols each)

    wmma::fragment<wmma::accumulator, 16, 16, 16, float> c[4][4];
    #pragma unroll
    for (int mi = 0; mi < 4; mi++)
        #pragma unroll
        for (int ni = 0; ni < 4; ni++)
            wmma::fill_fragment(c[mi][ni], 0.0f);

    auto stage = [&](int it) {
        const int buf = it % NST;
        const int k0  = it * BK;
        __half* as = As + buf * ASTG;
        #pragma unroll
        for (int i = 0; i < 4; i++) {
            int ch  = tid + i * 128;
            int row = ch >> 2;
            int c8  = ch & 3;
            cp16(as + row * APADh + c8 * 8,
                 A + (size_t)(m0 + row) * lda + k0 + c8 * 8);
        }
        __half* bs = Bs + buf * BSTG;
        if (BCOL) {
            #pragma unroll
            for (int i = 0; i < 4; i++) {
                int ch  = tid + i * 128;
                int row = ch >> 2;
                int c8  = ch & 3;
                cp16(bs + row * APADh + c8 * 8,
                     B + (size_t)(n0 + row) * ldb + k0 + c8 * 8);
            }
        } else {
            #pragma unroll
            for (int i = 0; i < 4; i++) {
                int ch  = tid + i * 128;
                int row = ch >> 4;
                int c8  = ch & 15;
                cp16(bs + row * BNPADh + c8 * 8,
                     B + (size_t)(k0 + row) * ldb + n0 + c8 * 8);
            }
        }
    };

    const int T = K / BK;
    stage(0); cp_commit();
    stage(1); cp_commit();

    for (int it = 0; it < T; it++) {
        if (it + 2 < T) stage(it + 2);
        cp_commit();
        cp_wait2();
        __syncthreads();

        const __half* as = As + (it % NST) * ASTG;
        const __half* bs = Bs + (it % NST) * BSTG;

        #pragma unroll
        for (int kk = 0; kk < BK; kk += 16) {
            wmma::fragment<wmma::matrix_a, 16, 16, 16, __half, wmma::row_major> a[4];
            #pragma unroll
            for (int mi = 0; mi < 4; mi++)
                wmma::load_matrix_sync(a[mi], as + (warp_m * 64 + mi * 16) * APADh + kk, APADh);
            if (BCOL) {
                wmma::fragment<wmma::matrix_b, 16, 16, 16, __half, wmma::col_major> b[4];
                #pragma unroll
                for (int ni = 0; ni < 4; ni++)
                    wmma::load_matrix_sync(b[ni], bs + (warp_n * 64 + ni * 16) * APADh + kk, APADh);
                #pragma unroll
                for (int mi = 0; mi < 4; mi++)
                    #pragma unroll
                    for (int ni = 0; ni < 4; ni++)
                        wmma::mma_sync(c[mi][ni], a[mi], b[ni], c[mi][ni]);
            } else {
                wmma::fragment<wmma::matrix_b, 16, 16, 16, __half, wmma::row_major> b[4];
                #pragma unroll
                for (int ni = 0; ni < 4; ni++)
                    wmma::load_matrix_sync(b[ni], bs + kk * BNPADh + warp_n * 64 + ni * 16, BNPADh);
                #pragma unroll
                for (int mi = 0; mi < 4; mi++)
                    #pragma unroll
                    for (int ni = 0; ni < 4; ni++)
                        wmma::mma_sync(c[mi][ni], a[mi], b[ni], c[mi][ni]);
            }
        }
        __syncthreads();
    }

    // --- epilogue ---
    #pragma unroll
    for (int mi = 0; mi < 4; mi++) {
        #pragma unroll
        for (int ni = 0; ni < 4; ni++) {
            OutT* Cp = C + (size_t)(m0 + warp_m * 64 + mi * 16) * ldc
                         + n0 + warp_n * 64 + ni * 16;
            if constexpr (std::is_same<OutT, float>::value) {
                #pragma unroll
                for (int t = 0; t < c[mi][ni].num_elements; t++)
                    c[mi][ni].x[t] *= alpha;
                wmma::store_matrix_sync(Cp, c[mi][ni], ldc, wmma::mem_row_major);
            } else {
                wmma::fragment<wmma::accumulator, 16, 16, 16, __half> hc;
                #pragma unroll
                for (int t = 0; t < hc.num_elements; t++)
                    hc.x[t] = __float2half(c[mi][ni].x[t] * alpha);
                wmma::store_matrix_sync(Cp, hc, ldc, wmma::mem_row_major);
            }
        }
    }
}

static inline int gemm_smem_bytes(bool bcol) {
    int astg = BM * APADh;
    int bstg = bcol ? (BM * APADh) : (BK * BNPADh);
    return (int)(NST * (astg + bstg) * sizeof(__half));
}

// ---------------- score GEMM with fused mask + exp + row-partial-sum epilogue ----
// Per (h,b): S = exp(mask ? -inf : Q K^T / sqrt(dh)) -> attns (unnormalized exp, fp32)
// plus partial row sums to g_partial[row][16] (CTA x-tile * 2 + warp_n), deterministic.
// Epilogue ldm for the smem roundtrip buffer:
#define ELD 72
#define SCORE_SMEM (4 * 64 * ELD * 4)   // 73728 B (>= staging 61440 B, reused)

__global__ __launch_bounds__(128, 2)
void score_gemm(const __half* __restrict__ Qbase,
                const __half* __restrict__ Kbase,
                float* __restrict__ attns,
                float* __restrict__ partial,
                const void* __restrict__ mask,
                float alpha)
{
    extern __shared__ __align__(16) __half smh[];
    constexpr int ASTG = BM * APADh;
    __half* As = smh;
    __half* Bs = smh + NST * ASTG;

    const int z = blockIdx.z;            // h*8 + b
    const int b = z & (BATCH - 1);
    const int h = z >> 3;
    const __half* A = Qbase + (size_t)h * DH + (size_t)b * SQ * D_;         // lda 1024
    const __half* B = Kbase + (size_t)h * DH + (size_t)b * SK * 2 * D_;     // ldb 2048
    float*        C = attns + (size_t)z * SQ * SK;

    const int m0 = blockIdx.y * BM;
    const int n0 = blockIdx.x * BN;

    const int tid    = threadIdx.x;
    const int wid    = tid >> 5;
    const int lane   = tid & 31;
    const int warp_m = wid & 1;
    const int warp_n = wid >> 1;

    wmma::fragment<wmma::accumulator, 16, 16, 16, float> c[4][4];
    #pragma unroll
    for (int mi = 0; mi < 4; mi++)
        #pragma unroll
        for (int ni = 0; ni < 4; ni++)
            wmma::fill_fragment(c[mi][ni], 0.0f);

    auto stage = [&](int it) {
        const int buf = it % NST;
        const int k0  = it * BK;
        __half* as = As + buf * ASTG;
        #pragma unroll
        for (int i = 0; i < 4; i++) {
            int ch  = tid + i * 128;
            int row = ch >> 2;
            int c8  = ch & 3;
            cp16(as + row * APADh + c8 * 8,
                 A + (size_t)(m0 + row) * D_ + k0 + c8 * 8);
        }
        __half* bs = Bs + buf * ASTG;
        #pragma unroll
        for (int i = 0; i < 4; i++) {
            int ch  = tid + i * 128;
            int row = ch >> 2;
            int c8  = ch & 3;
            cp16(bs + row * APADh + c8 * 8,
                 B + (size_t)(n0 + row) * (2 * D_) + k0 + c8 * 8);
        }
    };

    const int T = DH / BK;   // 4
    stage(0); cp_commit();
    stage(1); cp_commit();

    for (int it = 0; it < T; it++) {
        if (it + 2 < T) stage(it + 2);
        cp_commit();
        cp_wait2();
        __syncthreads();

        const __half* as = As + (it % NST) * ASTG;
        const __half* bs = Bs + (it % NST) * ASTG;

        #pragma unroll
        for (int kk = 0; kk < BK; kk += 16) {
            wmma::fragment<wmma::matrix_a, 16, 16, 16, __half, wmma::row_major> a[4];
            #pragma unroll
            for (int mi = 0; mi < 4; mi++)
                wmma::load_matrix_sync(a[mi], as + (warp_m * 64 + mi * 16) * APADh + kk, APADh);
            wmma::fragment<wmma::matrix_b, 16, 16, 16, __half, wmma::col_major> bfr[4];
            #pragma unroll
            for (int ni = 0; ni < 4; ni++)
                wmma::load_matrix_sync(bfr[ni], bs + (warp_n * 64 + ni * 16) * APADh + kk, APADh);
            #pragma unroll
            for (int mi = 0; mi < 4; mi++)
                #pragma unroll
                for (int ni = 0; ni < 4; ni++)
                    wmma::mma_sync(c[mi][ni], a[mi], bfr[ni], c[mi][ni]);
        }
        __syncthreads();
    }

    // ---- fused epilogue: smem roundtrip -> mask + exp + partial row sums ----
    float* ebuf = reinterpret_cast<float*>(smh);
    float* wbuf = ebuf + wid * 64 * ELD;
    #pragma unroll
    for (int mi = 0; mi < 4; mi++)
        #pragma unroll
        for (int ni = 0; ni < 4; ni++)
            wmma::store_matrix_sync(wbuf + (mi * 16) * ELD + ni * 16,
                                    c[mi][ni], ELD, wmma::mem_row_major);
    __syncwarp();

    const int kind  = g_mask_kind;
    const int rsel  = lane >> 4;       // 0/1: which of the 2 rows this iter
    const int c4    = lane & 15;       // float4 index within 64-col slice
    const int col   = c4 * 4;
    const int m_b   = m0 + warp_m * 64;
    const int n_b   = n0 + warp_n * 64;

    #pragma unroll 4
    for (int it2 = 0; it2 < 32; it2++) {
        const int row = it2 * 2 + rsel;
        const int gq  = m_b + row;
        const int gc  = n_b + col;
        float4 v = *reinterpret_cast<float4*>(wbuf + row * ELD + col);
        v.x *= alpha; v.y *= alpha; v.z *= alpha; v.w *= alpha;
        v.x = __expf(v.x); v.y = __expf(v.y); v.z = __expf(v.z); v.w = __expf(v.w);
        const size_t moff = ((size_t)b * SQ + gq) * SK + gc;
        if (kind == 0) {
            int4 m = *reinterpret_cast<const int4*>((const int*)mask + moff);
            if (m.x) v.x = 0.0f;
            if (m.y) v.y = 0.0f;
            if (m.z) v.z = 0.0f;
            if (m.w) v.w = 0.0f;
        } else if (kind == 1) {
            uchar4 m = *reinterpret_cast<const uchar4*>((const unsigned char*)mask + moff);
            if (m.x) v.x = 0.0f;
            if (m.y) v.y = 0.0f;
            if (m.z) v.z = 0.0f;
            if (m.w) v.w = 0.0f;
        } else {
            float4 m = *reinterpret_cast<const float4*>((const float*)mask + moff);
            if (m.x != 0.0f) v.x = 0.0f;
            if (m.y != 0.0f) v.y = 0.0f;
            if (m.z != 0.0f) v.z = 0.0f;
            if (m.w != 0.0f) v.w = 0.0f;
        }
        float s4 = (v.x + v.y) + (v.z + v.w);
        #pragma unroll
        for (int o = 8; o > 0; o >>= 1)
            s4 += __shfl_xor_sync(0xffffffffu, s4, o);   // reduce within 16-lane group
        if (c4 == 0)
            partial[((size_t)z * SQ + gq) * 16 + blockIdx.x * 2 + warp_n] = s4;
        *reinterpret_cast<float4*>(C + (size_t)gq * SK + gc) = v;
    }
}

// ---------------- mask dtype detection ----------------
__global__ void detect_mask_kernel(const unsigned* __restrict__ m) {
    __shared__ int votes[2];  // [0]=byte, [1]=float
    if (threadIdx.x < 2) votes[threadIdx.x] = 0;
    __syncthreads();
    for (int i = threadIdx.x; i < 2048; i += blockDim.x) {
        unsigned w = m[i];
        if (w > 1u) {
            if (w == 0x3F800000u) atomicOr(&votes[1], 1);
            else                  atomicOr(&votes[0], 1);
        }
    }
    __syncthreads();
    if (threadIdx.x == 0)
        g_mask_kind = votes[0] ? 1 : (votes[1] ? 2 : 0);
}

// ---------------- normalize: attns(exp) -> softmax * qmask, fp32 + fp16 ----------------
__global__ __launch_bounds__(256)
void normalize_kernel(float* __restrict__ attns, __half* __restrict__ ph,
                      const float* __restrict__ partial,
                      const float* __restrict__ qmask)
{
    const int r = blockIdx.x;            // 0 .. 65535
    const int q = r & (SQ - 1);
    const int b = (r >> 10) & (BATCH - 1);
    const int t = threadIdx.x;

    __shared__ float ssum;
    if (t < 32) {
        float v = (t < 16) ? partial[(size_t)r * 16 + t] : 0.0f;
        #pragma unroll
        for (int o = 8; o > 0; o >>= 1) v += __shfl_xor_sync(0xffffffffu, v, o);
        if (t == 0) ssum = v;
    }
    __syncthreads();
    const float scale = qmask[b * SQ + q] / ssum;

    float4* row4 = reinterpret_cast<float4*>(attns + (size_t)r * SK);
    float4 p = row4[t];
    p.x *= scale; p.y *= scale; p.z *= scale; p.w *= scale;
    row4[t] = p;

    __half2 h0 = __floats2half2_rn(p.x, p.y);
    __half2 h1 = __floats2half2_rn(p.z, p.w);
    uint2 u;
    u.x = *reinterpret_cast<unsigned*>(&h0);
    u.y = *reinterpret_cast<unsigned*>(&h1);
    *reinterpret_cast<uint2*>(ph + (size_t)r * SK + 4 * t) = u;
}

// ---------------- residual + bias + LayerNorm (float4) ----------------
__global__ __launch_bounds__(256)
void ln_kernel(const float* __restrict__ y, const float* __restrict__ dec,
               const float* __restrict__ bf, const float* __restrict__ gamma,
               const float* __restrict__ beta, float* __restrict__ out)
{
    const size_t base4 = ((size_t)blockIdx.x * D_) >> 2;
    const int t = threadIdx.x;
    const float4 y4 = reinterpret_cast<const float4*>(y)[base4 + t];
    const float4 d4 = reinterpret_cast<const float4*>(dec)[base4 + t];
    const float4 b4 = reinterpret_cast<const float4*>(bf)[t];
    float4 x;
    x.x = y4.x + b4.x + d4.x;
    x.y = y4.y + b4.y + d4.y;
    x.z = y4.z + b4.z + d4.z;
    x.w = y4.w + b4.w + d4.w;

    float s  = (x.x + x.y) + (x.z + x.w);
    float ss = (x.x * x.x + x.y * x.y) + (x.z * x.z + x.w * x.w);
    s  = blockReduceSum(s);
    ss = blockReduceSum(ss);
    const float mu   = s * (1.0f / D_);
    const float var  = ss * (1.0f / D_) - mu * mu;
    const float rstd = rsqrtf(var + 1e-5f);

    const float4 g4  = reinterpret_cast<const float4*>(gamma)[t];
    const float4 be4 = reinterpret_cast<const float4*>(beta)[t];
    float4 o;
    o.x = (x.x - mu) * rstd * g4.x + be4.x;
    o.y = (x.y - mu) * rstd * g4.y + be4.y;
    o.z = (x.z - mu) * rstd * g4.z + be4.z;
    o.w = (x.w - mu) * rstd * g4.w + be4.w;
    reinterpret_cast<float4*>(out)[base4 + t] = o;
}

// ---------------- launcher ----------------
extern "C" void kernel_launch(void* const* d_in, const int* in_sizes, int n_in,
                              void* d_out, int out_size)
{
    (void)in_sizes; (void)n_in; (void)out_size;
    const float* memory = (const float*)d_in[0];
    const float* dec    = (const float*)d_in[1];
    const float* qmask  = (const float*)d_in[2];
    const float* Wk     = (const float*)d_in[3];
    const float* Wv     = (const float*)d_in[4];
    const float* Wq     = (const float*)d_in[5];
    const float* Wf     = (const float*)d_in[6];
    const float* bf     = (const float*)d_in[7];
    const float* gamma  = (const float*)d_in[8];
    const float* beta   = (const float*)d_in[9];
    const void*  mask   = d_in[10];

    float* out_x = (float*)d_out;
    float* attns = out_x + (size_t)BATCH * SQ * D_;   // x first, then attns

    __half *memH, *cat, *KVh, *Qh, *Ph, *Wh;
    float *gY, *gPart;
    cudaGetSymbolAddress((void**)&memH,  g_memH);
    cudaGetSymbolAddress((void**)&cat,   g_cat);
    cudaGetSymbolAddress((void**)&KVh,   g_KVh);
    cudaGetSymbolAddress((void**)&Qh,    g_Qh);
    cudaGetSymbolAddress((void**)&Ph,    g_Ph);
    cudaGetSymbolAddress((void**)&Wh,    g_Wh);
    cudaGetSymbolAddress((void**)&gY,    g_Y);
    cudaGetSymbolAddress((void**)&gPart, g_partial);
    __half* Wkvh = Wh;                               // [1024, 2048] packed [Wk|Wv]
    __half* Wqh  = Wh + (size_t)2 * 1024 * 1024;     // [1024, 1024]
    __half* Wfh  = Wh + (size_t)3 * 1024 * 1024;     // [2048, 1024]
    __half* Vh   = KVh + D_;                         // cols 1024-2047, ld 2048

    const int smemR = gemm_smem_bytes(false);
    cudaFuncSetAttribute(gemm_h<false, __half>,
                         cudaFuncAttributeMaxDynamicSharedMemorySize, smemR);
    cudaFuncSetAttribute(gemm_h<false, float>,
                         cudaFuncAttributeMaxDynamicSharedMemorySize, smemR);
    cudaFuncSetAttribute(score_gemm,
                         cudaFuncAttributeMaxDynamicSharedMemorySize, SCORE_SMEM);

    const dim3 blk(256);
    const dim3 gblk(128);
    const long long SqSk = (long long)SQ * SK;
    const long long SkD2 = (long long)SK * 2 * D_;
    const float inv_sqrt_dh = 0.08838834764831843f;  // 1/sqrt(128)

    // 0) conversions
    detect_mask_kernel<<<1, 256>>>((const unsigned*)mask);
    f2h_kernel<<<4096, blk>>>((const float4*)memory, (uint4*)memH, 1048576);
    dec2cat_kernel<<<4096, blk>>>((const float4*)dec, cat);
    wconv_kernel<<<2560, blk>>>((const float4*)Wk, (const float4*)Wv,
                                (const float4*)Wq, (const float4*)Wf,
                                (uint4*)Wh);

    // 1) fused K+V projection; Q projection
    gemm_h<false, __half><<<dim3(16, 64, 1), gblk, smemR>>>(
        memH, 0, 0, D_, Wkvh, 0, 0, 2 * D_, KVh, 0, 0, 2 * D_, D_, 1, 1.0f);
    gemm_h<false, __half><<<dim3(8, 64, 1), gblk, smemR>>>(
        cat, 0, 0, 2 * D_, Wqh, 0, 0, D_, Qh, 0, 0, D_, D_, 1, 1.0f);

    // 2) scores + fused mask/exp/partial-sums -> attns holds unnormalized exp
    score_gemm<<<dim3(8, 8, NH * BATCH), gblk, SCORE_SMEM>>>(
        Qh, KVh, attns, gPart, mask, inv_sqrt_dh);

    // 3) normalize: attns = exp/sum * qmask (fp32 output) + fp16 Ph
    normalize_kernel<<<NH * BATCH * SQ, 256>>>(attns, Ph, gPart, qmask);

    // 4) attn @ V -> right half of cat (fp16)
    gemm_h<false, __half><<<dim3(1, 8, NH * BATCH), gblk, smemR>>>(
        Ph, (long long)BATCH * SqSk, SqSk, SK,
        Vh, DH, SkD2, 2 * D_,
        cat + D_, DH, (long long)SQ * 2 * D_, 2 * D_,
        SK, BATCH, 1.0f);

    // 5) Y = cat @ Wf   (K = 2048, fp32 out)
    gemm_h<false, float><<<dim3(8, 64, 1), gblk, smemR>>>(
        cat, 0, 0, 2 * D_, Wfh, 0, 0, D_, gY, 0, 0, D_, 2 * D_, 1, 1.0f);

    // 6) residual + bias + LayerNorm -> x output
    ln_kernel<<<BATCH * SQ, 256>>>(gY, dec, bf, gamma, beta, out_x);
}

// round 17
// speedup vs baseline: 1.3020x; 1.3020x over previous
#include <cuda_runtime.h>
#include <cuda_fp16.h>
#include <mma.h>
#include <cstdint>
#include <type_traits>

using namespace nvcuda;

// Problem dims (fixed by the dataset)
#define D_    1024
#define SQ    1024
#define SK    1024
#define BATCH 8
#define NH    8
#define DH    128

#define NEGV  (-4294967295.0f)   // -2^32 + 1

// ---------------- scratch (device globals: no allocation allowed) ----------------
__device__ __half g_memH[(size_t)BATCH * SK * D_];        // fp16(memory)            [8192,1024]
__device__ __half g_cat[(size_t)BATCH * SQ * 2 * D_];     // [fp16(dec) | attn@V]    [8192,2048]
__device__ __half g_KVh[(size_t)BATCH * SK * 2 * D_];     // [K | V] packed          [8192,2048]
__device__ __half g_Qh[(size_t)BATCH * SQ * D_];          // fp16(dec @ Wq)
__device__ __half g_Ph[(size_t)NH * BATCH * SQ * SK];     // fp16(softmax(attn))     128MB
__device__ __half g_Wh[(size_t)5 * 1024 * 1024];          // [Wk|Wv] packed 2M | Wq 1M | Wf 2M
__device__ float  g_Y[(size_t)BATCH * SQ * D_];           // concat @ Wf (fp32)
__device__ int    g_mask_kind;                            // 0=int32, 1=byte, 2=float32

// ---------------- helpers ----------------
__device__ __forceinline__ void cp16(void* smem_dst, const void* gsrc) {
    uint32_t s = (uint32_t)__cvta_generic_to_shared(smem_dst);
    asm volatile("cp.async.cg.shared.global [%0], [%1], 16;\n" :: "r"(s), "l"(gsrc));
}
__device__ __forceinline__ void cp_commit() { asm volatile("cp.async.commit_group;\n"); }
__device__ __forceinline__ void cp_wait2()  { asm volatile("cp.async.wait_group 2;\n"); }

// ---------------- reductions ----------------
__device__ __forceinline__ float blockReduceSum(float v) {
    __shared__ float sh[8];
    __syncthreads();
    #pragma unroll
    for (int o = 16; o > 0; o >>= 1) v += __shfl_xor_sync(0xffffffffu, v, o);
    int lane = threadIdx.x & 31, w = threadIdx.x >> 5;
    if (lane == 0) sh[w] = v;
    __syncthreads();
    if (w == 0) {
        float x = (lane < 8) ? sh[lane] : 0.0f;
        #pragma unroll
        for (int o = 4; o > 0; o >>= 1) x += __shfl_xor_sync(0xffffffffu, x, o);
        if (lane == 0) sh[0] = x;
    }
    __syncthreads();
    return sh[0];
}

// ---------------- fp32 -> fp16 pack helper ----------------
__device__ __forceinline__ uint4 pack_h8(float4 a, float4 b) {
    __half2 h0 = __floats2half2_rn(a.x, a.y);
    __half2 h1 = __floats2half2_rn(a.z, a.w);
    __half2 h2 = __floats2half2_rn(b.x, b.y);
    __half2 h3 = __floats2half2_rn(b.z, b.w);
    uint4 u;
    u.x = *reinterpret_cast<unsigned*>(&h0);
    u.y = *reinterpret_cast<unsigned*>(&h1);
    u.z = *reinterpret_cast<unsigned*>(&h2);
    u.w = *reinterpret_cast<unsigned*>(&h3);
    return u;
}

// memory fp32 -> fp16 (8 elems/thread)
__global__ __launch_bounds__(256)
void f2h_kernel(const float4* __restrict__ in, uint4* __restrict__ out, int n8)
{
    int i = blockIdx.x * 256 + threadIdx.x;
    if (i < n8) out[i] = pack_h8(in[2 * i], in[2 * i + 1]);
}

// dec fp32 [8192,1024] -> fp16 into left half of cat [8192,2048]
__global__ __launch_bounds__(256)
void dec2cat_kernel(const float4* __restrict__ dec, __half* __restrict__ cat)
{
    int i = blockIdx.x * 256 + threadIdx.x;     // 1M threads, 8 elems each
    int row = i >> 7, c8 = i & 127;
    uint4 u = pack_h8(dec[2 * i], dec[2 * i + 1]);
    *reinterpret_cast<uint4*>(cat + (size_t)row * 2048 + c8 * 8) = u;
}

// Weight conversion into packed fp16 layouts (Wkv [1024,2048] | Wq | Wf)
__global__ __launch_bounds__(256)
void wconv_kernel(const float4* __restrict__ Wk, const float4* __restrict__ Wv,
                  const float4* __restrict__ Wq, const float4* __restrict__ Wf,
                  uint4* __restrict__ Wh)
{
    int i = blockIdx.x * 256 + threadIdx.x;     // 0 .. 655359  (5M halfs / 8)
    const float4* src;
    int j;
    if (i < 262144) {                  // Wkv packed region: [1024, 2048] halfs
        int row = i >> 8;
        int c8  = i & 255;
        if (c8 < 128) { src = Wk; j = row * 128 + c8; }
        else          { src = Wv; j = row * 128 + (c8 - 128); }
    } else if (i < 393216) { src = Wq; j = i - 262144; }
    else                   { src = Wf; j = i - 393216; }
    Wh[i] = pack_h8(src[2 * j], src[2 * j + 1]);
}

// ---------------- generic batched fp16 wmma GEMM ----------------
// 128 threads / 4 warps, BM=BN=128, warp tile 64x64 (4x4 fragments), BK=32.
// C[z][M,N] = alpha * A[z][M,K] * B[z][K,N], fp32 accumulate.
// A row-major fp16. B row-major fp16 if !BCOL, else B(k,n)=Bptr[n*ldb+k].
// OutT = float (direct store) or __half (round epilogue).
// Requires: M%128==0, N%128==0, K%32==0, K/32 >= 3, 16B-aligned pointers & lds.

#define BM 128
#define BN 128
#define BK 32
#define APADh  40    // halfs: 80B row stride (16B multiple)
#define BNPADh 136   // halfs: 272B row stride (16B multiple)
#define NST 3

template<bool BCOL, typename OutT>
__global__ __launch_bounds__(128, 2)
void gemm_h(const __half* __restrict__ Abase, long long sA1, long long sA2, int lda,
            const __half* __restrict__ Bbase, long long sB1, long long sB2, int ldb,
            OutT*         __restrict__ Cbase, long long sC1, long long sC2, int ldc,
            int K, int Z2, float alpha)
{
    extern __shared__ __align__(16) __half smh[];
    constexpr int ASTG = BM * APADh;                        // 5120 halfs
    constexpr int BSTG = BCOL ? (BM * APADh) : (BK * BNPADh);
    __half* As = smh;
    __half* Bs = smh + NST * ASTG;

    const int z  = blockIdx.z;
    const int z1 = z / Z2, z2 = z % Z2;
    const __half* A = Abase + (size_t)z1 * sA1 + (size_t)z2 * sA2;
    const __half* B = Bbase + (size_t)z1 * sB1 + (size_t)z2 * sB2;
    OutT*         C = Cbase + (size_t)z1 * sC1 + (size_t)z2 * sC2;

    const int m0 = blockIdx.y * BM;
    const int n0 = blockIdx.x * BN;

    const int tid    = threadIdx.x;
    const int wid    = tid >> 5;
    const int warp_m = wid & 1;   // 2 warps along M (64 rows each)
    const int warp_n = wid >> 1;  // 2 warps along N (64 cols each)

    wmma::fragment<wmma::accumulator, 16, 16, 16, float> c[4][4];
    #pragma unroll
    for (int mi = 0; mi < 4; mi++)
        #pragma unroll
        for (int ni = 0; ni < 4; ni++)
            wmma::fill_fragment(c[mi][ni], 0.0f);

    auto stage = [&](int it) {
        const int buf = it % NST;
        const int k0  = it * BK;
        __half* as = As + buf * ASTG;
        #pragma unroll
        for (int i = 0; i < 4; i++) {           // A: 512 chunks (128 rows x 4x16B)
            int ch  = tid + i * 128;
            int row = ch >> 2;
            int c8  = ch & 3;
            cp16(as + row * APADh + c8 * 8,
                 A + (size_t)(m0 + row) * lda + k0 + c8 * 8);
        }
        __half* bs = Bs + buf * BSTG;
        if (BCOL) {
            #pragma unroll
            for (int i = 0; i < 4; i++) {       // Bs[n][k]: 128 rows x 4x16B
                int ch  = tid + i * 128;
                int row = ch >> 2;
                int c8  = ch & 3;
                cp16(bs + row * APADh + c8 * 8,
                     B + (size_t)(n0 + row) * ldb + k0 + c8 * 8);
            }
        } else {
            #pragma unroll
            for (int i = 0; i < 4; i++) {       // Bs[k][n]: 32 rows x 16x16B
                int ch  = tid + i * 128;
                int row = ch >> 4;
                int c8  = ch & 15;
                cp16(bs + row * BNPADh + c8 * 8,
                     B + (size_t)(k0 + row) * ldb + n0 + c8 * 8);
            }
        }
    };

    const int T = K / BK;       // >= 3 for all our GEMMs (min K = 128)
    stage(0); cp_commit();
    stage(1); cp_commit();

    for (int it = 0; it < T; it++) {
        if (it + 2 < T) stage(it + 2);
        cp_commit();                 // unconditional: keeps group accounting aligned
        cp_wait2();                  // slab `it` fully landed
        __syncthreads();

        const __half* as = As + (it % NST) * ASTG;
        const __half* bs = Bs + (it % NST) * BSTG;

        #pragma unroll
        for (int kk = 0; kk < BK; kk += 16) {
            wmma::fragment<wmma::matrix_a, 16, 16, 16, __half, wmma::row_major> a[4];
            #pragma unroll
            for (int mi = 0; mi < 4; mi++)
                wmma::load_matrix_sync(a[mi], as + (warp_m * 64 + mi * 16) * APADh + kk, APADh);
            if (BCOL) {
                wmma::fragment<wmma::matrix_b, 16, 16, 16, __half, wmma::col_major> b[4];
                #pragma unroll
                for (int ni = 0; ni < 4; ni++)
                    wmma::load_matrix_sync(b[ni], bs + (warp_n * 64 + ni * 16) * APADh + kk, APADh);
                #pragma unroll
                for (int mi = 0; mi < 4; mi++)
                    #pragma unroll
                    for (int ni = 0; ni < 4; ni++)
                        wmma::mma_sync(c[mi][ni], a[mi], b[ni], c[mi][ni]);
            } else {
                wmma::fragment<wmma::matrix_b, 16, 16, 16, __half, wmma::row_major> b[4];
                #pragma unroll
                for (int ni = 0; ni < 4; ni++)
                    wmma::load_matrix_sync(b[ni], bs + kk * BNPADh + warp_n * 64 + ni * 16, BNPADh);
                #pragma unroll
                for (int mi = 0; mi < 4; mi++)
                    #pragma unroll
                    for (int ni = 0; ni < 4; ni++)
                        wmma::mma_sync(c[mi][ni], a[mi], b[ni], c[mi][ni]);
            }
        }
        __syncthreads();
    }

    // --- epilogue ---
    #pragma unroll
    for (int mi = 0; mi < 4; mi++) {
        #pragma unroll
        for (int ni = 0; ni < 4; ni++) {
            OutT* Cp = C + (size_t)(m0 + warp_m * 64 + mi * 16) * ldc
                         + n0 + warp_n * 64 + ni * 16;
            if constexpr (std::is_same<OutT, float>::value) {
                #pragma unroll
                for (int t = 0; t < c[mi][ni].num_elements; t++)
                    c[mi][ni].x[t] *= alpha;
                wmma::store_matrix_sync(Cp, c[mi][ni], ldc, wmma::mem_row_major);
            } else {
                wmma::fragment<wmma::accumulator, 16, 16, 16, __half> hc;
                #pragma unroll
                for (int t = 0; t < hc.num_elements; t++)
                    hc.x[t] = __float2half(c[mi][ni].x[t] * alpha);
                wmma::store_matrix_sync(Cp, hc, ldc, wmma::mem_row_major);
            }
        }
    }
}

static inline int gemm_smem_bytes(bool bcol) {
    int astg = BM * APADh;
    int bstg = bcol ? (BM * APADh) : (BK * BNPADh);
    return (int)(NST * (astg + bstg) * sizeof(__half));
}

// ---------------- mask dtype detection ----------------
__global__ void detect_mask_kernel(const unsigned* __restrict__ m) {
    __shared__ int votes[2];  // [0]=byte, [1]=float
    if (threadIdx.x < 2) votes[threadIdx.x] = 0;
    __syncthreads();
    for (int i = threadIdx.x; i < 2048; i += blockDim.x) {
        unsigned w = m[i];
        if (w > 1u) {
            if (w == 0x3F800000u) atomicOr(&votes[1], 1);
            else                  atomicOr(&votes[0], 1);
        }
    }
    __syncthreads();
    if (threadIdx.x == 0)
        g_mask_kind = votes[0] ? 1 : (votes[1] ? 2 : 0);
}

// ---------------- masked softmax + query-mask (no max pass) ----------------
// Scores are bounded (|s| < ~8 pre-mask), so exp() is fp32-safe without the
// max-subtraction; exp(NEGV) underflows to exactly 0 for masked entries.
// Reads raw fp32 scores from attns, writes fp32 attns (output) + fp16 copy.
__global__ __launch_bounds__(256)
void softmax_kernel(float* __restrict__ attns, __half* __restrict__ ph,
                    const void* __restrict__ mask,
                    const float* __restrict__ qmask)
{
    const int r  = blockIdx.x;           // 0 .. 64*1024-1
    const int q  = r & (SQ - 1);
    const int hb = r >> 10;
    const int b  = hb & (BATCH - 1);
    float4* row4 = reinterpret_cast<float4*>(attns + (size_t)r * SK);
    const size_t m4 = (((size_t)b * SQ + q) * (size_t)SK) >> 2;
    const int t = threadIdx.x;
    const int kind = g_mask_kind;

    float4 v = row4[t];
    if (kind == 0) {
        int4 m = reinterpret_cast<const int4*>(mask)[m4 + t];
        if (m.x) v.x = NEGV;
        if (m.y) v.y = NEGV;
        if (m.z) v.z = NEGV;
        if (m.w) v.w = NEGV;
    } else if (kind == 1) {
        uchar4 m = reinterpret_cast<const uchar4*>(mask)[m4 + t];
        if (m.x) v.x = NEGV;
        if (m.y) v.y = NEGV;
        if (m.z) v.z = NEGV;
        if (m.w) v.w = NEGV;
    } else {
        float4 m = reinterpret_cast<const float4*>(mask)[m4 + t];
        if (m.x != 0.0f) v.x = NEGV;
        if (m.y != 0.0f) v.y = NEGV;
        if (m.z != 0.0f) v.z = NEGV;
        if (m.w != 0.0f) v.w = NEGV;
    }

    float4 p;
    p.x = __expf(v.x);
    p.y = __expf(v.y);
    p.z = __expf(v.z);
    p.w = __expf(v.w);
    float s = (p.x + p.y) + (p.z + p.w);
    s = blockReduceSum(s);

    const float scale = qmask[b * SQ + q] / s;
    p.x *= scale; p.y *= scale; p.z *= scale; p.w *= scale;
    row4[t] = p;

    __half2 h0 = __floats2half2_rn(p.x, p.y);
    __half2 h1 = __floats2half2_rn(p.z, p.w);
    uint2 u;
    u.x = *reinterpret_cast<unsigned*>(&h0);
    u.y = *reinterpret_cast<unsigned*>(&h1);
    *reinterpret_cast<uint2*>(ph + (size_t)r * SK + 4 * t) = u;
}

// ---------------- residual + bias + LayerNorm (float4) ----------------
__global__ __launch_bounds__(256)
void ln_kernel(const float* __restrict__ y, const float* __restrict__ dec,
               const float* __restrict__ bf, const float* __restrict__ gamma,
               const float* __restrict__ beta, float* __restrict__ out)
{
    const size_t base4 = ((size_t)blockIdx.x * D_) >> 2;
    const int t = threadIdx.x;
    const float4 y4 = reinterpret_cast<const float4*>(y)[base4 + t];
    const float4 d4 = reinterpret_cast<const float4*>(dec)[base4 + t];
    const float4 b4 = reinterpret_cast<const float4*>(bf)[t];
    float4 x;
    x.x = y4.x + b4.x + d4.x;
    x.y = y4.y + b4.y + d4.y;
    x.z = y4.z + b4.z + d4.z;
    x.w = y4.w + b4.w + d4.w;

    float s  = (x.x + x.y) + (x.z + x.w);
    float ss = (x.x * x.x + x.y * x.y) + (x.z * x.z + x.w * x.w);
    s  = blockReduceSum(s);
    ss = blockReduceSum(ss);
    const float mu   = s * (1.0f / D_);
    const float var  = ss * (1.0f / D_) - mu * mu;
    const float rstd = rsqrtf(var + 1e-5f);

    const float4 g4  = reinterpret_cast<const float4*>(gamma)[t];
    const float4 be4 = reinterpret_cast<const float4*>(beta)[t];
    float4 o;
    o.x = (x.x - mu) * rstd * g4.x + be4.x;
    o.y = (x.y - mu) * rstd * g4.y + be4.y;
    o.z = (x.z - mu) * rstd * g4.z + be4.z;
    o.w = (x.w - mu) * rstd * g4.w + be4.w;
    reinterpret_cast<float4*>(out)[base4 + t] = o;
}

// ---------------- launcher ----------------
extern "C" void kernel_launch(void* const* d_in, const int* in_sizes, int n_in,
                              void* d_out, int out_size)
{
    (void)in_sizes; (void)n_in; (void)out_size;
    const float* memory = (const float*)d_in[0];
    const float* dec    = (const float*)d_in[1];
    const float* qmask  = (const float*)d_in[2];
    const float* Wk     = (const float*)d_in[3];
    const float* Wv     = (const float*)d_in[4];
    const float* Wq     = (const float*)d_in[5];
    const float* Wf     = (const float*)d_in[6];
    const float* bf     = (const float*)d_in[7];
    const float* gamma  = (const float*)d_in[8];
    const float* beta   = (const float*)d_in[9];
    const void*  mask   = d_in[10];

    float* out_x = (float*)d_out;
    float* attns = out_x + (size_t)BATCH * SQ * D_;   // x first, then attns

    __half *memH, *cat, *KVh, *Qh, *Ph, *Wh;
    float* gY;
    cudaGetSymbolAddress((void**)&memH, g_memH);
    cudaGetSymbolAddress((void**)&cat,  g_cat);
    cudaGetSymbolAddress((void**)&KVh,  g_KVh);
    cudaGetSymbolAddress((void**)&Qh,   g_Qh);
    cudaGetSymbolAddress((void**)&Ph,   g_Ph);
    cudaGetSymbolAddress((void**)&Wh,   g_Wh);
    cudaGetSymbolAddress((void**)&gY,   g_Y);
    __half* Wkvh = Wh;                               // [1024, 2048] packed [Wk|Wv]
    __half* Wqh  = Wh + (size_t)2 * 1024 * 1024;     // [1024, 1024]
    __half* Wfh  = Wh + (size_t)3 * 1024 * 1024;     // [2048, 1024]
    __half* Kh   = KVh;                              // [8192, 2048] cols 0-1023, ld 2048
    __half* Vh   = KVh + D_;                         // cols 1024-2047, ld 2048

    const int smemR = gemm_smem_bytes(false);
    const int smemC = gemm_smem_bytes(true);
    cudaFuncSetAttribute(gemm_h<false, __half>,
                         cudaFuncAttributeMaxDynamicSharedMemorySize, smemR);
    cudaFuncSetAttribute(gemm_h<false, float>,
                         cudaFuncAttributeMaxDynamicSharedMemorySize, smemR);
    cudaFuncSetAttribute(gemm_h<true, float>,
                         cudaFuncAttributeMaxDynamicSharedMemorySize, smemC);

    const dim3 blk(256);
    const dim3 gblk(128);
    const long long SqD  = (long long)SQ * D_;
    const long long SkD2 = (long long)SK * 2 * D_;    // KV buffer batch stride
    const long long SqSk = (long long)SQ * SK;
    const float inv_sqrt_dh = 0.08838834764831843f;  // 1/sqrt(128)

    // 0) conversions
    detect_mask_kernel<<<1, 256>>>((const unsigned*)mask);
    f2h_kernel<<<4096, blk>>>((const float4*)memory, (uint4*)memH, 1048576);
    dec2cat_kernel<<<4096, blk>>>((const float4*)dec, cat);
    wconv_kernel<<<2560, blk>>>((const float4*)Wk, (const float4*)Wv,
                                (const float4*)Wq, (const float4*)Wf,
                                (uint4*)Wh);

    // 1) fused K+V projection: [8192,1024] x [1024,2048] -> KVh [8192,2048]
    gemm_h<false, __half><<<dim3(16, 64, 1), gblk, smemR>>>(
        memH, 0, 0, D_, Wkvh, 0, 0, 2 * D_, KVh, 0, 0, 2 * D_, D_, 1, 1.0f);
    //    Q projection: [8192,2048(cat,left half)] x [1024,1024] -> Qh
    gemm_h<false, __half><<<dim3(8, 64, 1), gblk, smemR>>>(
        cat, 0, 0, 2 * D_, Wqh, 0, 0, D_, Qh, 0, 0, D_, D_, 1, 1.0f);

    // 2) scores: per (h,b): S = Q_hb @ K_hb^T / sqrt(dh) -> attns (raw fp32)
    gemm_h<true, float><<<dim3(8, 8, NH * BATCH), gblk, smemC>>>(
        Qh, DH, SqD, D_,
        Kh, DH, SkD2, 2 * D_,
        attns, (long long)BATCH * SqSk, SqSk, SK,
        DH, BATCH, inv_sqrt_dh);

    // 3) masked softmax + query-mask -> fp32 attns (output) + fp16 Ph
    softmax_kernel<<<NH * BATCH * SQ, 256>>>(attns, Ph, mask, qmask);

    // 4) attn @ V: per (h,b): [1024,1024] x [1024,128] -> right half of cat (fp16)
    gemm_h<false, __half><<<dim3(1, 8, NH * BATCH), gblk, smemR>>>(
        Ph, (long long)BATCH * SqSk, SqSk, SK,
        Vh, DH, SkD2, 2 * D_,
        cat + D_, DH, (long long)SQ * 2 * D_, 2 * D_,
        SK, BATCH, 1.0f);

    // 5) Y = cat @ Wf   (K = 2048, fp32 out)
    gemm_h<false, float><<<dim3(8, 64, 1), gblk, smemR>>>(
        cat, 0, 0, 2 * D_, Wfh, 0, 0, D_, gY, 0, 0, D_, 2 * D_, 1, 1.0f);

    // 6) residual + bias + LayerNorm -> x output (exact fp32 dec residual)
    ln_kernel<<<BATCH * SQ, 256>>>(gY, dec, bf, gamma, beta, out_x);
}